// round 3
// baseline (speedup 1.0000x reference)
#include <cuda_runtime.h>

// Problem constants
#define BB   2
#define SEQ  2048
#define DIMM 768
#define NH   12
#define HD   64

// ---------------------------------------------------------------------------
// Scratch (device globals: cudaMalloc is banned)
// ---------------------------------------------------------------------------
__device__ float g_Q[BB * SEQ * DIMM];                 // [4096][768]
__device__ float g_K[BB * SEQ * DIMM];
__device__ float g_V[BB * SEQ * DIMM];
__device__ float g_E[100663296];                       // [b,h,q,k] = 2*12*2048*2048 (403 MB)
__device__ float g_Dinv[8388608];                      // [b,q,k]   = 2*2048*2048   (34 MB)

// ---------------------------------------------------------------------------
// Packed f32x2 helpers (sm_103a FFMA2 — ptxas never auto-fuses; PTX only)
// ---------------------------------------------------------------------------
typedef unsigned long long u64;

__device__ __forceinline__ u64 pk2(float lo, float hi) {
    u64 r;
    asm("mov.b64 %0, {%1, %2};" : "=l"(r) : "f"(lo), "f"(hi));
    return r;
}
__device__ __forceinline__ void fma2(u64 &c, u64 a, u64 b) {
    asm("fma.rn.f32x2 %0, %1, %2, %0;" : "+l"(c) : "l"(a), "l"(b));
}
__device__ __forceinline__ float2 upk2(u64 v) {
    float lo, hi;
    asm("mov.b64 {%0, %1}, %2;" : "=f"(lo), "=f"(hi) : "l"(v));
    return make_float2(lo, hi);
}

// ---------------------------------------------------------------------------
// Kernel 1: Q/K/V = X @ W^T   (GEMM-NT, M=4096, N=768, K=768)
// CTA tile 128x128, BK=8, 256 threads, 8x8 per thread (2x2 quadrants of 4x4)
// ---------------------------------------------------------------------------
__global__ void __launch_bounds__(256, 2) k_qkv(
    const float* __restrict__ X,
    const float* __restrict__ Wq,
    const float* __restrict__ Wk,
    const float* __restrict__ Wv)
{
    const float* W = (blockIdx.z == 0) ? Wq : (blockIdx.z == 1) ? Wk : Wv;
    float*       O = (blockIdx.z == 0) ? g_Q : (blockIdx.z == 1) ? g_K : g_V;

    __shared__ float As[8][132];   // [k][m], stride 132 -> conflict-free staging
    __shared__ float Bs[8][132];   // [k][n]

    const int tid = threadIdx.x;
    const int m0 = blockIdx.y * 128;
    const int n0 = blockIdx.x * 128;
    const int lr = tid >> 1;            // 0..127 load row
    const int lc = (tid & 1) << 2;      // 0 or 4 load k-col
    const int ty = tid >> 4;            // 0..15 -> rows ty*4 (+64)
    const int tx = tid & 15;            // 0..15 -> cols tx*4 (+64)

    const float* Ap = X + (size_t)(m0 + lr) * DIMM + lc;
    const float* Bp = W + (size_t)(n0 + lr) * DIMM + lc;

    u64 cc[8][4];
    #pragma unroll
    for (int r = 0; r < 8; r++)
        #pragma unroll
        for (int p = 0; p < 4; p++) cc[r][p] = 0ull;

    float4 ar = *(const float4*)Ap;
    float4 br = *(const float4*)Bp;

    for (int kt = 0; kt < DIMM; kt += 8) {
        As[lc + 0][lr] = ar.x; As[lc + 1][lr] = ar.y;
        As[lc + 2][lr] = ar.z; As[lc + 3][lr] = ar.w;
        Bs[lc + 0][lr] = br.x; Bs[lc + 1][lr] = br.y;
        Bs[lc + 2][lr] = br.z; Bs[lc + 3][lr] = br.w;
        __syncthreads();
        if (kt + 8 < DIMM) {
            ar = *(const float4*)(Ap + kt + 8);
            br = *(const float4*)(Bp + kt + 8);
        }
        #pragma unroll
        for (int k = 0; k < 8; k++) {
            float4 a0 = *(const float4*)&As[k][ty * 4];
            float4 a1 = *(const float4*)&As[k][ty * 4 + 64];
            float4 b0 = *(const float4*)&Bs[k][tx * 4];
            float4 b1 = *(const float4*)&Bs[k][tx * 4 + 64];
            u64 bp[4] = { pk2(b0.x, b0.y), pk2(b0.z, b0.w),
                          pk2(b1.x, b1.y), pk2(b1.z, b1.w) };
            float av[8] = { a0.x, a0.y, a0.z, a0.w, a1.x, a1.y, a1.z, a1.w };
            #pragma unroll
            for (int r = 0; r < 8; r++) {
                u64 as = pk2(av[r], av[r]);
                fma2(cc[r][0], as, bp[0]);
                fma2(cc[r][1], as, bp[1]);
                fma2(cc[r][2], as, bp[2]);
                fma2(cc[r][3], as, bp[3]);
            }
        }
        __syncthreads();
    }

    #pragma unroll
    for (int r = 0; r < 8; r++) {
        int m = m0 + ((r & 4) << 4) + ty * 4 + (r & 3);
        float2 p0 = upk2(cc[r][0]), p1 = upk2(cc[r][1]);
        float2 p2 = upk2(cc[r][2]), p3 = upk2(cc[r][3]);
        *(float4*)(O + (size_t)m * DIMM + n0 + tx * 4)      = make_float4(p0.x, p0.y, p1.x, p1.y);
        *(float4*)(O + (size_t)m * DIMM + n0 + 64 + tx * 4) = make_float4(p2.x, p2.y, p3.x, p3.y);
    }
}

// ---------------------------------------------------------------------------
// Kernel 2: E[b,h,q,k] = exp(Q[b,h,q,:] . K[b,h,k,:])   (GEMM-NT, K=64)
// Same tiling as k_qkv; operands are 64-wide slices of g_Q/g_K (stride 768).
// ---------------------------------------------------------------------------
__global__ void __launch_bounds__(256, 2) k_escore()
{
    const int bh = blockIdx.z;
    const int b  = bh / NH;
    const int h  = bh % NH;
    const float* A  = g_Q + (size_t)b * SEQ * DIMM + h * HD;
    const float* Bm = g_K + (size_t)b * SEQ * DIMM + h * HD;

    __shared__ float As[8][132];
    __shared__ float Bs[8][132];

    const int tid = threadIdx.x;
    const int m0 = blockIdx.y * 128;   // q tile
    const int n0 = blockIdx.x * 128;   // k tile
    const int lr = tid >> 1;
    const int lc = (tid & 1) << 2;
    const int ty = tid >> 4;
    const int tx = tid & 15;

    const float* Ap = A  + (size_t)(m0 + lr) * DIMM + lc;
    const float* Bp = Bm + (size_t)(n0 + lr) * DIMM + lc;

    u64 cc[8][4];
    #pragma unroll
    for (int r = 0; r < 8; r++)
        #pragma unroll
        for (int p = 0; p < 4; p++) cc[r][p] = 0ull;

    float4 ar = *(const float4*)Ap;
    float4 br = *(const float4*)Bp;

    for (int kt = 0; kt < HD; kt += 8) {
        As[lc + 0][lr] = ar.x; As[lc + 1][lr] = ar.y;
        As[lc + 2][lr] = ar.z; As[lc + 3][lr] = ar.w;
        Bs[lc + 0][lr] = br.x; Bs[lc + 1][lr] = br.y;
        Bs[lc + 2][lr] = br.z; Bs[lc + 3][lr] = br.w;
        __syncthreads();
        if (kt + 8 < HD) {
            ar = *(const float4*)(Ap + kt + 8);
            br = *(const float4*)(Bp + kt + 8);
        }
        #pragma unroll
        for (int k = 0; k < 8; k++) {
            float4 a0 = *(const float4*)&As[k][ty * 4];
            float4 a1 = *(const float4*)&As[k][ty * 4 + 64];
            float4 b0 = *(const float4*)&Bs[k][tx * 4];
            float4 b1 = *(const float4*)&Bs[k][tx * 4 + 64];
            u64 bp[4] = { pk2(b0.x, b0.y), pk2(b0.z, b0.w),
                          pk2(b1.x, b1.y), pk2(b1.z, b1.w) };
            float av[8] = { a0.x, a0.y, a0.z, a0.w, a1.x, a1.y, a1.z, a1.w };
            #pragma unroll
            for (int r = 0; r < 8; r++) {
                u64 as = pk2(av[r], av[r]);
                fma2(cc[r][0], as, bp[0]);
                fma2(cc[r][1], as, bp[1]);
                fma2(cc[r][2], as, bp[2]);
                fma2(cc[r][3], as, bp[3]);
            }
        }
        __syncthreads();
    }

    #pragma unroll
    for (int r = 0; r < 8; r++) {
        int m = m0 + ((r & 4) << 4) + ty * 4 + (r & 3);
        size_t row = ((size_t)bh * SEQ + m) * SEQ;
        float2 p0 = upk2(cc[r][0]), p1 = upk2(cc[r][1]);
        float2 p2 = upk2(cc[r][2]), p3 = upk2(cc[r][3]);
        float4 v0 = make_float4(__expf(p0.x), __expf(p0.y), __expf(p1.x), __expf(p1.y));
        float4 v1 = make_float4(__expf(p2.x), __expf(p2.y), __expf(p3.x), __expf(p3.y));
        *(float4*)(g_E + row + n0 + tx * 4)      = v0;
        *(float4*)(g_E + row + n0 + 64 + tx * 4) = v1;
    }
}

// ---------------------------------------------------------------------------
// Kernel 3: Dinv[b,q,k] = (1/sqrt(768)) / sum_h E[b,h,q,k]
// Pure memory pass: 403 MB read, 34 MB write.
// ---------------------------------------------------------------------------
__global__ void __launch_bounds__(256) k_dsum()
{
    const int i4  = blockIdx.x * 256 + threadIdx.x;  // 0 .. 2097151 (float4 units)
    const int b   = i4 >> 20;                        // SEQ*SEQ/4 = 2^20 per batch
    const int qk4 = i4 & 0xFFFFF;

    const float4* E4 = (const float4*)g_E;
    size_t base = (size_t)b * NH * 1048576 + qk4;

    float4 s = make_float4(0.f, 0.f, 0.f, 0.f);
    #pragma unroll
    for (int h = 0; h < NH; h++) {
        float4 v = E4[base + (size_t)h * 1048576];
        s.x += v.x; s.y += v.y; s.z += v.z; s.w += v.w;
    }
    const float RS = 0.03608439182435161f;   // 1/sqrt(768)
    ((float4*)g_Dinv)[(size_t)b * 1048576 + qk4] =
        make_float4(RS / s.x, RS / s.y, RS / s.z, RS / s.w);
}

// ---------------------------------------------------------------------------
// Kernel 4: out[b,q,h*64+d] = sum_k (E[b,h,q,k]*Dinv[b,q,k]) * V[b,k,h*64+d]
// CTA tile 128q x 64d, BK=16, 256 threads, thread tile 8q x 4d.
// ---------------------------------------------------------------------------
__global__ void __launch_bounds__(256, 2) k_av(float* __restrict__ out)
{
    const int bh = blockIdx.z;
    const int b  = bh / NH;
    const int h  = bh % NH;
    const int q0 = blockIdx.x * 128;

    __shared__ float Es[16][132];   // [kk][q]
    __shared__ float Vs[16][64];    // [kk][d]

    const int tid = threadIdx.x;
    const int lr = tid >> 1;            // 0..127 q-row for E/Dinv loads
    const int lc = (tid & 1) << 2;      // 0 or 4 k-col
    const int vr = tid >> 4;            // 0..15 kk-row for V loads
    const int vc = (tid & 15) << 2;     // 0..60 d-col
    const int ty = tid >> 4;            // q rows ty*4 (+64)
    const int tx = tid & 15;            // d cols tx*4

    const float* rE = g_E    + ((size_t)bh * SEQ + q0 + lr) * SEQ;
    const float* rD = g_Dinv + ((size_t)b  * SEQ + q0 + lr) * SEQ;
    const float* rV = g_V    + (size_t)b * SEQ * DIMM + h * HD + vc;

    u64 cc[8][2];
    #pragma unroll
    for (int r = 0; r < 8; r++) { cc[r][0] = 0ull; cc[r][1] = 0ull; }

    float4 pe0 = *(const float4*)(rE + lc);
    float4 pd0 = *(const float4*)(rD + lc);
    float4 pe1 = *(const float4*)(rE + lc + 8);
    float4 pd1 = *(const float4*)(rD + lc + 8);
    float4 pv  = *(const float4*)(rV + (size_t)vr * DIMM);

    for (int k0 = 0; k0 < SEQ; k0 += 16) {
        Es[lc + 0][lr] = pe0.x * pd0.x; Es[lc + 1][lr] = pe0.y * pd0.y;
        Es[lc + 2][lr] = pe0.z * pd0.z; Es[lc + 3][lr] = pe0.w * pd0.w;
        Es[lc + 8][lr] = pe1.x * pd1.x; Es[lc + 9][lr] = pe1.y * pd1.y;
        Es[lc +10][lr] = pe1.z * pd1.z; Es[lc +11][lr] = pe1.w * pd1.w;
        *(float4*)&Vs[vr][vc] = pv;
        __syncthreads();
        if (k0 + 16 < SEQ) {
            pe0 = *(const float4*)(rE + k0 + 16 + lc);
            pd0 = *(const float4*)(rD + k0 + 16 + lc);
            pe1 = *(const float4*)(rE + k0 + 16 + lc + 8);
            pd1 = *(const float4*)(rD + k0 + 16 + lc + 8);
            pv  = *(const float4*)(rV + (size_t)(k0 + 16 + vr) * DIMM);
        }
        #pragma unroll
        for (int kk = 0; kk < 16; kk++) {
            float4 a0 = *(const float4*)&Es[kk][ty * 4];
            float4 a1 = *(const float4*)&Es[kk][ty * 4 + 64];
            float4 bv = *(const float4*)&Vs[kk][tx * 4];
            u64 bp0 = pk2(bv.x, bv.y);
            u64 bp1 = pk2(bv.z, bv.w);
            float av[8] = { a0.x, a0.y, a0.z, a0.w, a1.x, a1.y, a1.z, a1.w };
            #pragma unroll
            for (int r = 0; r < 8; r++) {
                u64 as = pk2(av[r], av[r]);
                fma2(cc[r][0], as, bp0);
                fma2(cc[r][1], as, bp1);
            }
        }
        __syncthreads();
    }

    #pragma unroll
    for (int r = 0; r < 8; r++) {
        int q = q0 + ((r & 4) << 4) + ty * 4 + (r & 3);
        float2 p0 = upk2(cc[r][0]), p1 = upk2(cc[r][1]);
        *(float4*)(out + ((size_t)b * SEQ + q) * DIMM + h * HD + tx * 4) =
            make_float4(p0.x, p0.y, p1.x, p1.y);
    }
}

// ---------------------------------------------------------------------------
extern "C" void kernel_launch(void* const* d_in, const int* in_sizes, int n_in,
                              void* d_out, int out_size)
{
    const float* x  = (const float*)d_in[0];
    const float* wq = (const float*)d_in[1];
    const float* wk = (const float*)d_in[2];
    const float* wv = (const float*)d_in[3];
    float* out = (float*)d_out;

    k_qkv   <<<dim3(6, 32, 3),   256>>>(x, wq, wk, wv);
    k_escore<<<dim3(16, 16, 24), 256>>>();
    k_dsum  <<<8192,             256>>>();
    k_av    <<<dim3(16, 1, 24),  256>>>(out);
}

// round 4
// speedup vs baseline: 1.6644x; 1.6644x over previous
#include <cuda_runtime.h>

// Problem constants
#define BB   2
#define SEQ  2048
#define DIMM 768
#define NH   12
#define HD   64

// ---------------------------------------------------------------------------
// Scratch (device globals: cudaMalloc is banned)
// ---------------------------------------------------------------------------
__device__ float g_Q[BB * SEQ * DIMM];                 // [4096][768]
__device__ float g_K[BB * SEQ * DIMM];
__device__ float g_V[BB * SEQ * DIMM];
__device__ float g_E[100663296];                       // [b,h,q,k] (403 MB)
__device__ float g_Dinv[8388608];                      // [b,q,k]   (34 MB)

// ---------------------------------------------------------------------------
// Packed f32x2 helpers (sm_103a FFMA2 — ptxas never auto-fuses; PTX only)
// ---------------------------------------------------------------------------
typedef unsigned long long u64;

__device__ __forceinline__ u64 pk2(float lo, float hi) {
    u64 r;
    asm("mov.b64 %0, {%1, %2};" : "=l"(r) : "f"(lo), "f"(hi));
    return r;
}
__device__ __forceinline__ void fma2(u64 &c, u64 a, u64 b) {
    asm("fma.rn.f32x2 %0, %1, %2, %0;" : "+l"(c) : "l"(a), "l"(b));
}
__device__ __forceinline__ float2 upk2(u64 v) {
    float lo, hi;
    asm("mov.b64 {%0, %1}, %2;" : "=f"(lo), "=f"(hi) : "l"(v));
    return make_float2(lo, hi);
}
__device__ __forceinline__ float selh(u64 v, int h) {
    float2 f = upk2(v);
    return h ? f.y : f.x;
}

// ---------------------------------------------------------------------------
// Kernel 1: Q/K/V = X @ W^T   (GEMM-NT, M=4096, N=768, K=768)
// CTA 128x128, BK=8, 256 threads. Thread tile 8m x 8n, accumulators packed
// along m (pairs straight from LDS.128 of As; dup-MOVs only on b side).
// ---------------------------------------------------------------------------
__global__ void __launch_bounds__(256, 2) k_qkv(
    const float* __restrict__ X,
    const float* __restrict__ Wq,
    const float* __restrict__ Wk,
    const float* __restrict__ Wv)
{
    const float* W = (blockIdx.z == 0) ? Wq : (blockIdx.z == 1) ? Wk : Wv;
    float*       O = (blockIdx.z == 0) ? g_Q : (blockIdx.z == 1) ? g_K : g_V;

    __shared__ __align__(16) float As[8][132];   // [k][m]
    __shared__ __align__(16) float Bs[8][132];   // [k][n]

    const int tid = threadIdx.x;
    const int m0 = blockIdx.y * 128;
    const int n0 = blockIdx.x * 128;
    const int lr = tid >> 1;
    const int lc = (tid & 1) << 2;
    const int ty = tid >> 4;            // m rows ty*8 .. ty*8+7
    const int tx = tid & 15;            // n cols tx*4 (+64)

    const float* Ap = X + (size_t)(m0 + lr) * DIMM + lc;
    const float* Bp = W + (size_t)(n0 + lr) * DIMM + lc;

    u64 c[4][8];
    #pragma unroll
    for (int p = 0; p < 4; p++)
        #pragma unroll
        for (int j = 0; j < 8; j++) c[p][j] = 0ull;

    float4 ar = *(const float4*)Ap;
    float4 br = *(const float4*)Bp;

    for (int kt = 0; kt < DIMM; kt += 8) {
        As[lc + 0][lr] = ar.x; As[lc + 1][lr] = ar.y;
        As[lc + 2][lr] = ar.z; As[lc + 3][lr] = ar.w;
        Bs[lc + 0][lr] = br.x; Bs[lc + 1][lr] = br.y;
        Bs[lc + 2][lr] = br.z; Bs[lc + 3][lr] = br.w;
        __syncthreads();
        if (kt + 8 < DIMM) {
            ar = *(const float4*)(Ap + kt + 8);
            br = *(const float4*)(Bp + kt + 8);
        }
        #pragma unroll
        for (int k = 0; k < 8; k++) {
            ulonglong2 a01 = *(const ulonglong2*)&As[k][ty * 8];
            ulonglong2 a23 = *(const ulonglong2*)&As[k][ty * 8 + 4];
            float4 b0 = *(const float4*)&Bs[k][tx * 4];
            float4 b1 = *(const float4*)&Bs[k][tx * 4 + 64];
            u64 aa[4] = { a01.x, a01.y, a23.x, a23.y };
            u64 bb[8] = { pk2(b0.x, b0.x), pk2(b0.y, b0.y),
                          pk2(b0.z, b0.z), pk2(b0.w, b0.w),
                          pk2(b1.x, b1.x), pk2(b1.y, b1.y),
                          pk2(b1.z, b1.z), pk2(b1.w, b1.w) };
            #pragma unroll
            for (int p = 0; p < 4; p++)
                #pragma unroll
                for (int j = 0; j < 8; j++)
                    fma2(c[p][j], aa[p], bb[j]);
        }
        __syncthreads();
    }

    #pragma unroll
    for (int r = 0; r < 8; r++) {
        const int p = r >> 1, hh = r & 1;
        const int m = m0 + ty * 8 + r;
        float4 v0 = make_float4(selh(c[p][0], hh), selh(c[p][1], hh),
                                selh(c[p][2], hh), selh(c[p][3], hh));
        float4 v1 = make_float4(selh(c[p][4], hh), selh(c[p][5], hh),
                                selh(c[p][6], hh), selh(c[p][7], hh));
        *(float4*)(O + (size_t)m * DIMM + n0 + tx * 4)      = v0;
        *(float4*)(O + (size_t)m * DIMM + n0 + 64 + tx * 4) = v1;
    }
}

// ---------------------------------------------------------------------------
// Kernel 2: E[b,h,q,k] = exp(Q . K)   (GEMM-NT, K=64), same v2 microkernel.
// ---------------------------------------------------------------------------
__global__ void __launch_bounds__(256, 2) k_escore()
{
    const int bh = blockIdx.z;
    const int b  = bh / NH;
    const int h  = bh % NH;
    const float* A  = g_Q + (size_t)b * SEQ * DIMM + h * HD;
    const float* Bm = g_K + (size_t)b * SEQ * DIMM + h * HD;

    __shared__ __align__(16) float As[8][132];
    __shared__ __align__(16) float Bs[8][132];

    const int tid = threadIdx.x;
    const int m0 = blockIdx.y * 128;   // q tile
    const int n0 = blockIdx.x * 128;   // k tile
    const int lr = tid >> 1;
    const int lc = (tid & 1) << 2;
    const int ty = tid >> 4;
    const int tx = tid & 15;

    const float* Ap = A  + (size_t)(m0 + lr) * DIMM + lc;
    const float* Bp = Bm + (size_t)(n0 + lr) * DIMM + lc;

    u64 c[4][8];
    #pragma unroll
    for (int p = 0; p < 4; p++)
        #pragma unroll
        for (int j = 0; j < 8; j++) c[p][j] = 0ull;

    float4 ar = *(const float4*)Ap;
    float4 br = *(const float4*)Bp;

    for (int kt = 0; kt < HD; kt += 8) {
        As[lc + 0][lr] = ar.x; As[lc + 1][lr] = ar.y;
        As[lc + 2][lr] = ar.z; As[lc + 3][lr] = ar.w;
        Bs[lc + 0][lr] = br.x; Bs[lc + 1][lr] = br.y;
        Bs[lc + 2][lr] = br.z; Bs[lc + 3][lr] = br.w;
        __syncthreads();
        if (kt + 8 < HD) {
            ar = *(const float4*)(Ap + kt + 8);
            br = *(const float4*)(Bp + kt + 8);
        }
        #pragma unroll
        for (int k = 0; k < 8; k++) {
            ulonglong2 a01 = *(const ulonglong2*)&As[k][ty * 8];
            ulonglong2 a23 = *(const ulonglong2*)&As[k][ty * 8 + 4];
            float4 b0 = *(const float4*)&Bs[k][tx * 4];
            float4 b1 = *(const float4*)&Bs[k][tx * 4 + 64];
            u64 aa[4] = { a01.x, a01.y, a23.x, a23.y };
            u64 bb[8] = { pk2(b0.x, b0.x), pk2(b0.y, b0.y),
                          pk2(b0.z, b0.z), pk2(b0.w, b0.w),
                          pk2(b1.x, b1.x), pk2(b1.y, b1.y),
                          pk2(b1.z, b1.z), pk2(b1.w, b1.w) };
            #pragma unroll
            for (int p = 0; p < 4; p++)
                #pragma unroll
                for (int j = 0; j < 8; j++)
                    fma2(c[p][j], aa[p], bb[j]);
        }
        __syncthreads();
    }

    #pragma unroll
    for (int r = 0; r < 8; r++) {
        const int p = r >> 1, hh = r & 1;
        const int m = m0 + ty * 8 + r;
        size_t row = ((size_t)bh * SEQ + m) * SEQ;
        float4 v0 = make_float4(__expf(selh(c[p][0], hh)), __expf(selh(c[p][1], hh)),
                                __expf(selh(c[p][2], hh)), __expf(selh(c[p][3], hh)));
        float4 v1 = make_float4(__expf(selh(c[p][4], hh)), __expf(selh(c[p][5], hh)),
                                __expf(selh(c[p][6], hh)), __expf(selh(c[p][7], hh)));
        *(float4*)(g_E + row + n0 + tx * 4)      = v0;
        *(float4*)(g_E + row + n0 + 64 + tx * 4) = v1;
    }
}

// ---------------------------------------------------------------------------
// Kernel 3: Dinv[b,q,k] = (1/sqrt(768)) / sum_h E[b,h,q,k]
// ---------------------------------------------------------------------------
__global__ void __launch_bounds__(256) k_dsum()
{
    const int i4  = blockIdx.x * 256 + threadIdx.x;
    const int b   = i4 >> 20;
    const int qk4 = i4 & 0xFFFFF;

    const float4* E4 = (const float4*)g_E;
    size_t base = (size_t)b * NH * 1048576 + qk4;

    float4 s = make_float4(0.f, 0.f, 0.f, 0.f);
    #pragma unroll
    for (int h = 0; h < NH; h++) {
        float4 v = E4[base + (size_t)h * 1048576];
        s.x += v.x; s.y += v.y; s.z += v.z; s.w += v.w;
    }
    const float RS = 0.03608439182435161f;   // 1/sqrt(768)
    ((float4*)g_Dinv)[(size_t)b * 1048576 + qk4] =
        make_float4(RS / s.x, RS / s.y, RS / s.z, RS / s.w);
}

// ---------------------------------------------------------------------------
// Zero-init for the split-K reduction target.
// ---------------------------------------------------------------------------
__global__ void __launch_bounds__(256) k_zero(float* __restrict__ out)
{
    ((float4*)out)[blockIdx.x * 256 + threadIdx.x] = make_float4(0.f, 0.f, 0.f, 0.f);
}

// ---------------------------------------------------------------------------
// Kernel 4: out += (E * Dinv) @ V, split-K x4 (REDG epilogue).
// CTA 128q x 64d, BK=8, 256 threads, thread tile 8q x 4d, q-paired accum.
// ---------------------------------------------------------------------------
__global__ void __launch_bounds__(256, 3) k_av(float* __restrict__ out)
{
    const int bh = blockIdx.z;
    const int b  = bh / NH;
    const int h  = bh % NH;
    const int q0 = blockIdx.x * 128;
    const int kb = blockIdx.y * (SEQ / 4);   // split-K chunk base

    __shared__ __align__(16) float Es[8][132];   // [kk][q] = E*Dinv
    __shared__ __align__(16) float Vs[8][64];    // [kk][d]

    const int tid = threadIdx.x;
    const int lr = tid >> 1;            // q row for E/Dinv loads
    const int lc = (tid & 1) << 2;      // k col 0/4
    const int vr = tid >> 5;            // 0..7 kk row for V
    const int vc = (tid & 31) << 1;     // 0..62 d col (float2)
    const int ty = tid >> 4;            // q rows ty*8..+7
    const int tx = tid & 15;            // d cols tx*4

    const float* rE = g_E    + ((size_t)bh * SEQ + q0 + lr) * SEQ + kb;
    const float* rD = g_Dinv + ((size_t)b  * SEQ + q0 + lr) * SEQ + kb;
    const float* rV = g_V    + ((size_t)b * SEQ + kb + vr) * DIMM + h * HD + vc;

    u64 c[4][4];
    #pragma unroll
    for (int p = 0; p < 4; p++)
        #pragma unroll
        for (int j = 0; j < 4; j++) c[p][j] = 0ull;

    float4 pe = *(const float4*)(rE + lc);
    float4 pd = *(const float4*)(rD + lc);
    float2 pv = *(const float2*)rV;

    for (int k0 = 0; k0 < SEQ / 4; k0 += 8) {
        Es[lc + 0][lr] = pe.x * pd.x; Es[lc + 1][lr] = pe.y * pd.y;
        Es[lc + 2][lr] = pe.z * pd.z; Es[lc + 3][lr] = pe.w * pd.w;
        Vs[vr][vc] = pv.x; Vs[vr][vc + 1] = pv.y;
        __syncthreads();
        if (k0 + 8 < SEQ / 4) {
            pe = *(const float4*)(rE + k0 + 8 + lc);
            pd = *(const float4*)(rD + k0 + 8 + lc);
            pv = *(const float2*)(rV + (size_t)(k0 + 8) * DIMM);
        }
        #pragma unroll
        for (int kk = 0; kk < 8; kk++) {
            ulonglong2 a01 = *(const ulonglong2*)&Es[kk][ty * 8];
            ulonglong2 a23 = *(const ulonglong2*)&Es[kk][ty * 8 + 4];
            float4 bv = *(const float4*)&Vs[kk][tx * 4];
            u64 aa[4] = { a01.x, a01.y, a23.x, a23.y };
            u64 bb[4] = { pk2(bv.x, bv.x), pk2(bv.y, bv.y),
                          pk2(bv.z, bv.z), pk2(bv.w, bv.w) };
            #pragma unroll
            for (int p = 0; p < 4; p++)
                #pragma unroll
                for (int j = 0; j < 4; j++)
                    fma2(c[p][j], aa[p], bb[j]);
        }
        __syncthreads();
    }

    #pragma unroll
    for (int r = 0; r < 8; r++) {
        const int p = r >> 1, hh = r & 1;
        const int q = q0 + ty * 8 + r;
        float* po = out + ((size_t)b * SEQ + q) * DIMM + h * HD + tx * 4;
        atomicAdd(po + 0, selh(c[p][0], hh));
        atomicAdd(po + 1, selh(c[p][1], hh));
        atomicAdd(po + 2, selh(c[p][2], hh));
        atomicAdd(po + 3, selh(c[p][3], hh));
    }
}

// ---------------------------------------------------------------------------
extern "C" void kernel_launch(void* const* d_in, const int* in_sizes, int n_in,
                              void* d_out, int out_size)
{
    const float* x  = (const float*)d_in[0];
    const float* wq = (const float*)d_in[1];
    const float* wk = (const float*)d_in[2];
    const float* wv = (const float*)d_in[3];
    float* out = (float*)d_out;

    k_qkv   <<<dim3(6, 32, 3),   256>>>(x, wq, wk, wv);
    k_escore<<<dim3(16, 16, 24), 256>>>();
    k_dsum  <<<8192,             256>>>();
    k_zero  <<<3072,             256>>>(out);
    k_av    <<<dim3(16, 4, 24),  256>>>(out);
}

// round 7
// speedup vs baseline: 2.0313x; 1.2204x over previous
#include <cuda_runtime.h>
#include <cuda_bf16.h>
#include <cstdint>

// Problem constants
#define BB   2
#define SEQ  2048
#define DIMM 768
#define NH   12
#define HD   64

// ---------------------------------------------------------------------------
// Scratch (device globals: cudaMalloc is banned)
// ---------------------------------------------------------------------------
__device__ float         g_V [BB * SEQ * DIMM];           // fp32 V (pre-transpose)
__device__ __nv_bfloat16 g_Qh[24 * SEQ * HD];             // [bh][q][d] hi
__device__ __nv_bfloat16 g_Ql[24 * SEQ * HD];             // [bh][q][d] lo
__device__ __nv_bfloat16 g_Kh[24 * SEQ * HD];
__device__ __nv_bfloat16 g_Kl[24 * SEQ * HD];
__device__ __nv_bfloat16 g_Vth[24 * HD * SEQ];            // [bh][d][k] hi (transposed)
__device__ __nv_bfloat16 g_Vtl[24 * HD * SEQ];
__device__ float g_E[100663296];                          // [bh][q][k] (403 MB)
__device__ float g_Dinv[8388608];                         // [b][q][k]  (34 MB)

// ---------------------------------------------------------------------------
// Packed f32x2 helpers (for the fma-path QKV GEMM)
// ---------------------------------------------------------------------------
typedef unsigned long long u64;

__device__ __forceinline__ u64 pk2(float lo, float hi) {
    u64 r; asm("mov.b64 %0, {%1, %2};" : "=l"(r) : "f"(lo), "f"(hi)); return r;
}
__device__ __forceinline__ void fma2(u64 &c, u64 a, u64 b) {
    asm("fma.rn.f32x2 %0, %1, %2, %0;" : "+l"(c) : "l"(a), "l"(b));
}
__device__ __forceinline__ float2 upk2(u64 v) {
    float lo, hi; asm("mov.b64 {%0, %1}, %2;" : "=f"(lo), "=f"(hi) : "l"(v));
    return make_float2(lo, hi);
}
__device__ __forceinline__ float selh(u64 v, int h) {
    float2 f = upk2(v); return h ? f.y : f.x;
}

// ---------------------------------------------------------------------------
// bf16 split helpers
// ---------------------------------------------------------------------------
__device__ __forceinline__ unsigned pkbf(__nv_bfloat16 a, __nv_bfloat16 b) {
    return ((unsigned)__bfloat16_as_ushort(b) << 16) | (unsigned)__bfloat16_as_ushort(a);
}
__device__ __forceinline__ void bsplit4(float4 v, uint2 &hi, uint2 &lo) {
    __nv_bfloat16 h0 = __float2bfloat16(v.x);
    __nv_bfloat16 h1 = __float2bfloat16(v.y);
    __nv_bfloat16 h2 = __float2bfloat16(v.z);
    __nv_bfloat16 h3 = __float2bfloat16(v.w);
    __nv_bfloat16 l0 = __float2bfloat16(v.x - __bfloat162float(h0));
    __nv_bfloat16 l1 = __float2bfloat16(v.y - __bfloat162float(h1));
    __nv_bfloat16 l2 = __float2bfloat16(v.z - __bfloat162float(h2));
    __nv_bfloat16 l3 = __float2bfloat16(v.w - __bfloat162float(h3));
    hi.x = pkbf(h0, h1); hi.y = pkbf(h2, h3);
    lo.x = pkbf(l0, l1); lo.y = pkbf(l2, l3);
}

// ---------------------------------------------------------------------------
// Portable tensor-core plumbing: ldmatrix + mma.sync (sm_80+ ISA, runs on
// sm_103 baseline target — tcgen05 is rejected by this toolchain's ptxas).
// ---------------------------------------------------------------------------
__device__ __forceinline__ uint32_t smem_u32(const void* p) {
    uint32_t a;
    asm("{ .reg .u64 t; cvta.to.shared.u64 t, %1; cvt.u32.u64 %0, t; }" : "=r"(a) : "l"(p));
    return a;
}
__device__ __forceinline__ void ldsm4(uint32_t* r, uint32_t addr) {
    asm volatile("ldmatrix.sync.aligned.m8n8.x4.shared.b16 {%0,%1,%2,%3}, [%4];"
                 : "=r"(r[0]), "=r"(r[1]), "=r"(r[2]), "=r"(r[3]) : "r"(addr));
}
__device__ __forceinline__ void mma16816(float* c, const uint32_t* a,
                                         uint32_t b0, uint32_t b1) {
    asm volatile(
        "mma.sync.aligned.m16n8k16.row.col.f32.bf16.bf16.f32 "
        "{%0,%1,%2,%3}, {%4,%5,%6,%7}, {%8,%9}, {%0,%1,%2,%3};"
        : "+f"(c[0]), "+f"(c[1]), "+f"(c[2]), "+f"(c[3])
        : "r"(a[0]), "r"(a[1]), "r"(a[2]), "r"(a[3]), "r"(b0), "r"(b1));
}

// Padded SMEM tile geometry: rows of 64 bf16 padded to 72 (144B stride).
// 144 = 16B*9 -> successive rows shift 4 banks; 8 ldmatrix rows cover all 32
// banks conflict-free.
#define TPAD_B 144

// ---------------------------------------------------------------------------
// Kernel 1: QKV projection (fma path) — epilogue emits bf16 hi/lo Q,K + fp32 V
// ---------------------------------------------------------------------------
__global__ void __launch_bounds__(256, 2) k_qkv(
    const float* __restrict__ X,
    const float* __restrict__ Wq,
    const float* __restrict__ Wk,
    const float* __restrict__ Wv)
{
    const float* W = (blockIdx.z == 0) ? Wq : (blockIdx.z == 1) ? Wk : Wv;

    __shared__ __align__(16) float As[8][132];
    __shared__ __align__(16) float Bs[8][132];

    const int tid = threadIdx.x;
    const int m0 = blockIdx.y * 128;
    const int n0 = blockIdx.x * 128;
    const int lr = tid >> 1;
    const int lc = (tid & 1) << 2;
    const int ty = tid >> 4;
    const int tx = tid & 15;

    const float* Ap = X + (size_t)(m0 + lr) * DIMM + lc;
    const float* Bp = W + (size_t)(n0 + lr) * DIMM + lc;

    u64 c[4][8];
    #pragma unroll
    for (int p = 0; p < 4; p++)
        #pragma unroll
        for (int j = 0; j < 8; j++) c[p][j] = 0ull;

    float4 ar = *(const float4*)Ap;
    float4 br = *(const float4*)Bp;

    for (int kt = 0; kt < DIMM; kt += 8) {
        As[lc + 0][lr] = ar.x; As[lc + 1][lr] = ar.y;
        As[lc + 2][lr] = ar.z; As[lc + 3][lr] = ar.w;
        Bs[lc + 0][lr] = br.x; Bs[lc + 1][lr] = br.y;
        Bs[lc + 2][lr] = br.z; Bs[lc + 3][lr] = br.w;
        __syncthreads();
        if (kt + 8 < DIMM) {
            ar = *(const float4*)(Ap + kt + 8);
            br = *(const float4*)(Bp + kt + 8);
        }
        #pragma unroll
        for (int k = 0; k < 8; k++) {
            ulonglong2 a01 = *(const ulonglong2*)&As[k][ty * 8];
            ulonglong2 a23 = *(const ulonglong2*)&As[k][ty * 8 + 4];
            float4 b0 = *(const float4*)&Bs[k][tx * 4];
            float4 b1 = *(const float4*)&Bs[k][tx * 4 + 64];
            u64 aa[4] = { a01.x, a01.y, a23.x, a23.y };
            u64 bb[8] = { pk2(b0.x, b0.x), pk2(b0.y, b0.y),
                          pk2(b0.z, b0.z), pk2(b0.w, b0.w),
                          pk2(b1.x, b1.x), pk2(b1.y, b1.y),
                          pk2(b1.z, b1.z), pk2(b1.w, b1.w) };
            #pragma unroll
            for (int p = 0; p < 4; p++)
                #pragma unroll
                for (int j = 0; j < 8; j++)
                    fma2(c[p][j], aa[p], bb[j]);
        }
        __syncthreads();
    }

    if (blockIdx.z == 2) {
        #pragma unroll
        for (int r = 0; r < 8; r++) {
            const int p = r >> 1, hh = r & 1;
            const int m = m0 + ty * 8 + r;
            float4 v0 = make_float4(selh(c[p][0], hh), selh(c[p][1], hh),
                                    selh(c[p][2], hh), selh(c[p][3], hh));
            float4 v1 = make_float4(selh(c[p][4], hh), selh(c[p][5], hh),
                                    selh(c[p][6], hh), selh(c[p][7], hh));
            *(float4*)(g_V + (size_t)m * DIMM + n0 + tx * 4)      = v0;
            *(float4*)(g_V + (size_t)m * DIMM + n0 + 64 + tx * 4) = v1;
        }
    } else {
        __nv_bfloat16* OH = (blockIdx.z == 0) ? g_Qh : g_Kh;
        __nv_bfloat16* OL = (blockIdx.z == 0) ? g_Ql : g_Kl;
        #pragma unroll
        for (int r = 0; r < 8; r++) {
            const int p = r >> 1, hh = r & 1;
            const int m = m0 + ty * 8 + r;
            const int b = m >> 11, q = m & 2047;
            #pragma unroll
            for (int half = 0; half < 2; half++) {
                float4 v = half
                    ? make_float4(selh(c[p][4], hh), selh(c[p][5], hh),
                                  selh(c[p][6], hh), selh(c[p][7], hh))
                    : make_float4(selh(c[p][0], hh), selh(c[p][1], hh),
                                  selh(c[p][2], hh), selh(c[p][3], hh));
                const int n = n0 + half * 64 + tx * 4;
                const int h = n >> 6, d = n & 63;
                size_t dst = ((size_t)(b * NH + h) * SEQ + q) * HD + d;
                uint2 hi, lo; bsplit4(v, hi, lo);
                *(uint2*)(OH + dst) = hi;
                *(uint2*)(OL + dst) = lo;
            }
        }
    }
}

// ---------------------------------------------------------------------------
// Kernel 1b: V transpose + split: g_V[b][k][h*64+d] -> g_Vth/l[bh][d][k]
// ---------------------------------------------------------------------------
__global__ void __launch_bounds__(256) k_vsplit()
{
    __shared__ float sh[64][65];
    const int tid = threadIdx.x;
    const int k0 = blockIdx.x * 64;
    const int bh = blockIdx.y;
    const int b = bh / NH, h = bh % NH;

    #pragma unroll
    for (int i = 0; i < 4; i++) {
        int idx4 = i * 256 + tid;
        int kk = idx4 >> 4, c4 = idx4 & 15;
        float4 v = *(const float4*)(g_V + ((size_t)(b * SEQ + k0 + kk)) * DIMM + h * HD + c4 * 4);
        sh[kk][c4 * 4 + 0] = v.x; sh[kk][c4 * 4 + 1] = v.y;
        sh[kk][c4 * 4 + 2] = v.z; sh[kk][c4 * 4 + 3] = v.w;
    }
    __syncthreads();
    #pragma unroll
    for (int i = 0; i < 2; i++) {
        int idx = i * 256 + tid;
        int d = idx >> 3, s = idx & 7;
        unsigned hw[4], lw[4];
        #pragma unroll
        for (int j = 0; j < 2; j++) {
            float4 v = make_float4(sh[s * 8 + j * 4 + 0][d], sh[s * 8 + j * 4 + 1][d],
                                   sh[s * 8 + j * 4 + 2][d], sh[s * 8 + j * 4 + 3][d]);
            uint2 hi, lo; bsplit4(v, hi, lo);
            hw[j * 2] = hi.x; hw[j * 2 + 1] = hi.y;
            lw[j * 2] = lo.x; lw[j * 2 + 1] = lo.y;
        }
        size_t dst = ((size_t)bh * HD + d) * SEQ + k0 + s * 8;
        *(uint4*)(g_Vth + dst) = make_uint4(hw[0], hw[1], hw[2], hw[3]);
        *(uint4*)(g_Vtl + dst) = make_uint4(lw[0], lw[1], lw[2], lw[3]);
    }
}

// ---------------------------------------------------------------------------
// Kernel 2: escore via mma.sync: E[bh][q][k] = exp(Q.K), bf16 3-MMA split.
// CTA 128q x 128k; 8 warps each 32q x 64k. Dyn smem: 4 tiles of 128x72 bf16.
// ---------------------------------------------------------------------------
#define ES_QH 0
#define ES_QL 18432
#define ES_KH 36864
#define ES_KL 55296
#define ES_SMEM 73728

__global__ void __launch_bounds__(256) k_escore_mma()
{
    extern __shared__ char smem[];
    const uint32_t sb = smem_u32(smem);
    const int tid = threadIdx.x, wid = tid >> 5, lane = tid & 31;
    const int bh = blockIdx.z;
    const int q0 = blockIdx.y * 128;
    const int k0 = blockIdx.x * 128;

    // Load 4 tiles: 128 rows x 64 bf16 (=8 uint4/row), padded to 144B rows
    {
        const __nv_bfloat16* srcs[4] = {
            g_Qh + ((size_t)bh * SEQ + q0) * HD, g_Ql + ((size_t)bh * SEQ + q0) * HD,
            g_Kh + ((size_t)bh * SEQ + k0) * HD, g_Kl + ((size_t)bh * SEQ + k0) * HD };
        const int offs[4] = { ES_QH, ES_QL, ES_KH, ES_KL };
        #pragma unroll
        for (int t = 0; t < 4; t++) {
            const uint4* src = (const uint4*)srcs[t];
            char* dst = smem + offs[t];
            #pragma unroll
            for (int i = 0; i < 4; i++) {
                int idx = i * 256 + tid;
                int row = idx >> 3, s = idx & 7;
                *(uint4*)(dst + row * TPAD_B + s * 16) = src[row * 8 + s];
            }
        }
    }
    __syncthreads();

    const int wq = (wid & 3) * 32;       // warp q-base within tile
    const int wk = (wid >> 2) * 64;      // warp k-base within tile

    float acc[2][8][4];
    #pragma unroll
    for (int mt = 0; mt < 2; mt++)
        #pragma unroll
        for (int nt = 0; nt < 8; nt++)
            #pragma unroll
            for (int j = 0; j < 4; j++) acc[mt][nt][j] = 0.f;

    const uint32_t a_roff = (lane & 15) * TPAD_B;
    const uint32_t a_coff = (lane >> 4) * 16;
    const uint32_t b_roff = ((lane & 7) + ((lane >> 3) & 1) * 8) * TPAD_B;
    const uint32_t b_coff = (lane >> 4) * 16;

    #pragma unroll
    for (int ks = 0; ks < 4; ks++) {
        uint32_t ah[2][4], al[2][4];
        #pragma unroll
        for (int mt = 0; mt < 2; mt++) {
            uint32_t base = (wq + mt * 16) * TPAD_B + ks * 32;
            ldsm4(ah[mt], sb + ES_QH + base + a_roff + a_coff);
            ldsm4(al[mt], sb + ES_QL + base + a_roff + a_coff);
        }
        #pragma unroll
        for (int ng = 0; ng < 4; ng++) {
            uint32_t base = (wk + ng * 16) * TPAD_B + ks * 32;
            uint32_t bhr[4], blr[4];
            ldsm4(bhr, sb + ES_KH + base + b_roff + b_coff);
            ldsm4(blr, sb + ES_KL + base + b_roff + b_coff);
            #pragma unroll
            for (int mt = 0; mt < 2; mt++) {
                mma16816(acc[mt][2 * ng],     ah[mt], bhr[0], bhr[2]);
                mma16816(acc[mt][2 * ng + 1], ah[mt], bhr[1], bhr[3]);
                mma16816(acc[mt][2 * ng],     ah[mt], blr[0], blr[2]);
                mma16816(acc[mt][2 * ng + 1], ah[mt], blr[1], blr[3]);
                mma16816(acc[mt][2 * ng],     al[mt], bhr[0], bhr[2]);
                mma16816(acc[mt][2 * ng + 1], al[mt], bhr[1], bhr[3]);
            }
        }
    }

    // Epilogue: exp + direct STG.64 (per instr: 8 rows x 32B full sectors)
    float* Eg = g_E + ((size_t)bh * SEQ + q0) * SEQ + k0;
    #pragma unroll
    for (int mt = 0; mt < 2; mt++) {
        const int r = wq + mt * 16 + (lane >> 2);
        #pragma unroll
        for (int nt = 0; nt < 8; nt++) {
            const int cc = wk + nt * 8 + (lane & 3) * 2;
            *(float2*)(Eg + (size_t)r * SEQ + cc) =
                make_float2(__expf(acc[mt][nt][0]), __expf(acc[mt][nt][1]));
            *(float2*)(Eg + (size_t)(r + 8) * SEQ + cc) =
                make_float2(__expf(acc[mt][nt][2]), __expf(acc[mt][nt][3]));
        }
    }
}

// ---------------------------------------------------------------------------
// Kernel 3: Dinv[b][q][k] = (1/sqrt(768)) / sum_h E[bh][q][k]
// ---------------------------------------------------------------------------
__global__ void __launch_bounds__(256) k_dsum()
{
    const int i4  = blockIdx.x * 256 + threadIdx.x;
    const int b   = i4 >> 20;
    const int qk4 = i4 & 0xFFFFF;

    const float4* E4 = (const float4*)g_E;
    size_t base = (size_t)b * NH * 1048576 + qk4;

    float4 s = make_float4(0.f, 0.f, 0.f, 0.f);
    #pragma unroll
    for (int h = 0; h < NH; h++) {
        float4 v = E4[base + (size_t)h * 1048576];
        s.x += v.x; s.y += v.y; s.z += v.z; s.w += v.w;
    }
    const float RS = 0.03608439182435161f;   // 1/sqrt(768)
    ((float4*)g_Dinv)[(size_t)b * 1048576 + qk4] =
        make_float4(RS / s.x, RS / s.y, RS / s.z, RS / s.w);
}

// ---------------------------------------------------------------------------
// Kernel 4: out = (E*Dinv) @ V via mma.sync, P split to bf16 on the fly.
// CTA 128q x 64d; 8 warps each 32q x 32d; K-loop 32 chunks of 64.
// Grid (h, qtile, b): heads sharing Dinv slice launch-adjacent (L2 reuse).
// ---------------------------------------------------------------------------
#define AV_PH 0
#define AV_PL 18432
#define AV_VH 36864
#define AV_VL 46080
#define AV_SMEM 55296

__global__ void __launch_bounds__(256) k_av_mma(float* __restrict__ out)
{
    extern __shared__ char smem[];
    const uint32_t sb = smem_u32(smem);
    const int tid = threadIdx.x, wid = tid >> 5, lane = tid & 31;
    const int h = blockIdx.x, b = blockIdx.z;
    const int bh = b * NH + h;
    const int q0 = blockIdx.y * 128;

    const float* Eb = g_E    + ((size_t)bh * SEQ + q0) * SEQ;
    const float* Db = g_Dinv + ((size_t)b  * SEQ + q0) * SEQ;
    const uint4* Vh4 = (const uint4*)(g_Vth + (size_t)bh * HD * SEQ);  // row pitch 256 uint4
    const uint4* Vl4 = (const uint4*)(g_Vtl + (size_t)bh * HD * SEQ);

    const int wq = (wid & 3) * 32;       // warp q-base
    const int wd = (wid >> 2) * 32;      // warp d-base

    float acc[2][4][4];
    #pragma unroll
    for (int mt = 0; mt < 2; mt++)
        #pragma unroll
        for (int nt = 0; nt < 4; nt++)
            #pragma unroll
            for (int j = 0; j < 4; j++) acc[mt][nt][j] = 0.f;

    const uint32_t a_roff = (lane & 15) * TPAD_B;
    const uint32_t a_coff = (lane >> 4) * 16;
    const uint32_t b_roff = ((lane & 7) + ((lane >> 3) & 1) * 8) * TPAD_B;
    const uint32_t b_coff = (lane >> 4) * 16;

    for (int kc = 0; kc < 32; kc++) {
        // V tiles [64d][64k] hi/lo
        #pragma unroll
        for (int i = 0; i < 2; i++) {
            int idx = i * 256 + tid;
            int d = idx >> 3, s = idx & 7;
            *(uint4*)(smem + AV_VH + d * TPAD_B + s * 16) = Vh4[d * 256 + kc * 8 + s];
            *(uint4*)(smem + AV_VL + d * TPAD_B + s * 16) = Vl4[d * 256 + kc * 8 + s];
        }
        // P tiles [128q][64k]: P = E*Dinv, split hi/lo
        #pragma unroll
        for (int i = 0; i < 8; i++) {
            int idx = i * 256 + tid;
            int r = idx >> 4, c4 = idx & 15;
            float4 e  = *(const float4*)(Eb + (size_t)r * SEQ + kc * 64 + c4 * 4);
            float4 dn = *(const float4*)(Db + (size_t)r * SEQ + kc * 64 + c4 * 4);
            float4 p = make_float4(e.x * dn.x, e.y * dn.y, e.z * dn.z, e.w * dn.w);
            uint2 hi, lo; bsplit4(p, hi, lo);
            *(uint2*)(smem + AV_PH + r * TPAD_B + c4 * 8) = hi;
            *(uint2*)(smem + AV_PL + r * TPAD_B + c4 * 8) = lo;
        }
        __syncthreads();

        #pragma unroll
        for (int ks = 0; ks < 4; ks++) {
            uint32_t ah[2][4], al[2][4];
            #pragma unroll
            for (int mt = 0; mt < 2; mt++) {
                uint32_t base = (wq + mt * 16) * TPAD_B + ks * 32;
                ldsm4(ah[mt], sb + AV_PH + base + a_roff + a_coff);
                ldsm4(al[mt], sb + AV_PL + base + a_roff + a_coff);
            }
            #pragma unroll
            for (int ng = 0; ng < 2; ng++) {
                uint32_t base = (wd + ng * 16) * TPAD_B + ks * 32;
                uint32_t bhr[4], blr[4];
                ldsm4(bhr, sb + AV_VH + base + b_roff + b_coff);
                ldsm4(blr, sb + AV_VL + base + b_roff + b_coff);
                #pragma unroll
                for (int mt = 0; mt < 2; mt++) {
                    mma16816(acc[mt][2 * ng],     ah[mt], bhr[0], bhr[2]);
                    mma16816(acc[mt][2 * ng + 1], ah[mt], bhr[1], bhr[3]);
                    mma16816(acc[mt][2 * ng],     ah[mt], blr[0], blr[2]);
                    mma16816(acc[mt][2 * ng + 1], ah[mt], blr[1], blr[3]);
                    mma16816(acc[mt][2 * ng],     al[mt], bhr[0], bhr[2]);
                    mma16816(acc[mt][2 * ng + 1], al[mt], bhr[1], bhr[3]);
                }
            }
        }
        __syncthreads();
    }

    // Epilogue: direct STG.64 into [b][q][h*64+d]
    float* Og = out + ((size_t)(b * SEQ + q0)) * DIMM + h * HD;
    #pragma unroll
    for (int mt = 0; mt < 2; mt++) {
        const int r = wq + mt * 16 + (lane >> 2);
        #pragma unroll
        for (int nt = 0; nt < 4; nt++) {
            const int cc = wd + nt * 8 + (lane & 3) * 2;
            *(float2*)(Og + (size_t)r * DIMM + cc) =
                make_float2(acc[mt][nt][0], acc[mt][nt][1]);
            *(float2*)(Og + (size_t)(r + 8) * DIMM + cc) =
                make_float2(acc[mt][nt][2], acc[mt][nt][3]);
        }
    }
}

// ---------------------------------------------------------------------------
extern "C" void kernel_launch(void* const* d_in, const int* in_sizes, int n_in,
                              void* d_out, int out_size)
{
    const float* x  = (const float*)d_in[0];
    const float* wq = (const float*)d_in[1];
    const float* wk = (const float*)d_in[2];
    const float* wv = (const float*)d_in[3];
    float* out = (float*)d_out;

    cudaFuncSetAttribute(k_escore_mma, cudaFuncAttributeMaxDynamicSharedMemorySize, ES_SMEM);
    cudaFuncSetAttribute(k_av_mma,     cudaFuncAttributeMaxDynamicSharedMemorySize, AV_SMEM);

    k_qkv       <<<dim3(6, 32, 3),   256>>>(x, wq, wk, wv);
    k_vsplit    <<<dim3(32, 24),     256>>>();
    k_escore_mma<<<dim3(16, 16, 24), 256, ES_SMEM>>>();
    k_dsum      <<<8192,             256>>>();
    k_av_mma    <<<dim3(12, 16, 2),  256, AV_SMEM>>>(out);
}

// round 8
// speedup vs baseline: 2.3902x; 1.1767x over previous
#include <cuda_runtime.h>
#include <cuda_bf16.h>
#include <cstdint>

// Problem constants
#define BB   2
#define SEQ  2048
#define DIMM 768
#define NH   12
#define HD   64

// ---------------------------------------------------------------------------
// Scratch (device globals: cudaMalloc is banned)
// ---------------------------------------------------------------------------
__device__ float         g_V [BB * SEQ * DIMM];           // fp32 V (pre-transpose)
__device__ __nv_bfloat16 g_Xh[BB * SEQ * DIMM];           // X hi/lo (for QKV GEMM)
__device__ __nv_bfloat16 g_Xl[BB * SEQ * DIMM];
__device__ __nv_bfloat16 g_Wh[3 * DIMM * DIMM];           // Wq|Wk|Wv hi/lo
__device__ __nv_bfloat16 g_Wl[3 * DIMM * DIMM];
__device__ __nv_bfloat16 g_Qh[24 * SEQ * HD];             // [bh][q][d] hi
__device__ __nv_bfloat16 g_Ql[24 * SEQ * HD];
__device__ __nv_bfloat16 g_Kh[24 * SEQ * HD];
__device__ __nv_bfloat16 g_Kl[24 * SEQ * HD];
__device__ __nv_bfloat16 g_Vth[24 * HD * SEQ];            // [bh][d][k] hi (transposed)
__device__ __nv_bfloat16 g_Vtl[24 * HD * SEQ];
__device__ float g_E[100663296];                          // [bh][q][k] (403 MB)
__device__ float g_Dinv[8388608];                         // [b][q][k]  (34 MB)

// ---------------------------------------------------------------------------
// bf16 split helpers
// ---------------------------------------------------------------------------
__device__ __forceinline__ unsigned pkbf(__nv_bfloat16 a, __nv_bfloat16 b) {
    return ((unsigned)__bfloat16_as_ushort(b) << 16) | (unsigned)__bfloat16_as_ushort(a);
}
__device__ __forceinline__ void bsplit4(float4 v, uint2 &hi, uint2 &lo) {
    __nv_bfloat16 h0 = __float2bfloat16(v.x);
    __nv_bfloat16 h1 = __float2bfloat16(v.y);
    __nv_bfloat16 h2 = __float2bfloat16(v.z);
    __nv_bfloat16 h3 = __float2bfloat16(v.w);
    __nv_bfloat16 l0 = __float2bfloat16(v.x - __bfloat162float(h0));
    __nv_bfloat16 l1 = __float2bfloat16(v.y - __bfloat162float(h1));
    __nv_bfloat16 l2 = __float2bfloat16(v.z - __bfloat162float(h2));
    __nv_bfloat16 l3 = __float2bfloat16(v.w - __bfloat162float(h3));
    hi.x = pkbf(h0, h1); hi.y = pkbf(h2, h3);
    lo.x = pkbf(l0, l1); lo.y = pkbf(l2, l3);
}
__device__ __forceinline__ unsigned bsplit2(float a, float b, unsigned &lo) {
    __nv_bfloat16 h0 = __float2bfloat16(a);
    __nv_bfloat16 h1 = __float2bfloat16(b);
    lo = pkbf(__float2bfloat16(a - __bfloat162float(h0)),
              __float2bfloat16(b - __bfloat162float(h1)));
    return pkbf(h0, h1);
}

// ---------------------------------------------------------------------------
// Portable tensor-core plumbing: ldmatrix + mma.sync (sm_80+ ISA — tcgen05 is
// rejected by the harness's compute_103 lowering).
// ---------------------------------------------------------------------------
__device__ __forceinline__ uint32_t smem_u32(const void* p) {
    uint32_t a;
    asm("{ .reg .u64 t; cvta.to.shared.u64 t, %1; cvt.u32.u64 %0, t; }" : "=r"(a) : "l"(p));
    return a;
}
__device__ __forceinline__ void ldsm4(uint32_t* r, uint32_t addr) {
    asm volatile("ldmatrix.sync.aligned.m8n8.x4.shared.b16 {%0,%1,%2,%3}, [%4];"
                 : "=r"(r[0]), "=r"(r[1]), "=r"(r[2]), "=r"(r[3]) : "r"(addr));
}
__device__ __forceinline__ void mma16816(float* c, const uint32_t* a,
                                         uint32_t b0, uint32_t b1) {
    asm volatile(
        "mma.sync.aligned.m16n8k16.row.col.f32.bf16.bf16.f32 "
        "{%0,%1,%2,%3}, {%4,%5,%6,%7}, {%8,%9}, {%0,%1,%2,%3};"
        : "+f"(c[0]), "+f"(c[1]), "+f"(c[2]), "+f"(c[3])
        : "r"(a[0]), "r"(a[1]), "r"(a[2]), "r"(a[3]), "r"(b0), "r"(b1));
}
__device__ __forceinline__ void cpa16(uint32_t dst, const void* src) {
    asm volatile("cp.async.cg.shared.global [%0], [%1], 16;"
                 :: "r"(dst), "l"((unsigned long long)__cvta_generic_to_global(src)));
}
#define CPA_COMMIT() asm volatile("cp.async.commit_group;" ::: "memory")
#define CPA_WAIT(n)  asm volatile("cp.async.wait_group %0;" :: "n"(n) : "memory")

// Padded SMEM tile geometry: rows of 64 bf16 padded to 72 (144B stride).
#define TPAD_B 144

// ---------------------------------------------------------------------------
// Kernel 0: split fp32 -> bf16 hi/lo (X and the three W matrices)
// ---------------------------------------------------------------------------
__global__ void __launch_bounds__(256) k_split(const float* __restrict__ src,
                                               __nv_bfloat16* __restrict__ dh,
                                               __nv_bfloat16* __restrict__ dl,
                                               int n4)
{
    int i = blockIdx.x * 256 + threadIdx.x;
    if (i >= n4) return;
    float4 v = ((const float4*)src)[i];
    uint2 hi, lo; bsplit4(v, hi, lo);
    *(uint2*)(dh + (size_t)i * 4) = hi;
    *(uint2*)(dl + (size_t)i * 4) = lo;
}

// ---------------------------------------------------------------------------
// Kernel 1: QKV projection via mma.sync 3-split: Y = X @ W^T.
// CTA 128m x 128n, 8 warps (32m x 64n), k-loop 12 chunks of 64.
// Epilogue: z<2 -> bf16 hi/lo Q/K in head-sliced layout; z=2 -> fp32 V.
// ---------------------------------------------------------------------------
#define QK_XH 0
#define QK_XL 18432
#define QK_WH 36864
#define QK_WL 55296
#define QK_SMEM 73728

__global__ void __launch_bounds__(256) k_qkv_mma()
{
    extern __shared__ char smem[];
    const uint32_t sb = smem_u32(smem);
    const int tid = threadIdx.x, wid = tid >> 5, lane = tid & 31;
    const int z  = blockIdx.z;
    const int m0 = blockIdx.y * 128;
    const int n0 = blockIdx.x * 128;

    const uint4* Xh4 = (const uint4*)(g_Xh + (size_t)m0 * DIMM);  // pitch 96 uint4
    const uint4* Xl4 = (const uint4*)(g_Xl + (size_t)m0 * DIMM);
    const uint4* Wh4 = (const uint4*)(g_Wh + ((size_t)z * DIMM + n0) * DIMM);
    const uint4* Wl4 = (const uint4*)(g_Wl + ((size_t)z * DIMM + n0) * DIMM);

    const int wq = (wid & 3) * 32;   // warp m-base
    const int wn = (wid >> 2) * 64;  // warp n-base

    float acc[2][8][4];
    #pragma unroll
    for (int mt = 0; mt < 2; mt++)
        #pragma unroll
        for (int nt = 0; nt < 8; nt++)
            #pragma unroll
            for (int j = 0; j < 4; j++) acc[mt][nt][j] = 0.f;

    const uint32_t a_roff = (lane & 15) * TPAD_B;
    const uint32_t a_coff = (lane >> 4) * 16;
    const uint32_t b_roff = ((lane & 7) + ((lane >> 3) & 1) * 8) * TPAD_B;
    const uint32_t b_coff = (lane >> 4) * 16;

    for (int kt = 0; kt < 12; kt++) {
        const uint4* srcs[4] = { Xh4, Xl4, Wh4, Wl4 };
        const int offs[4] = { QK_XH, QK_XL, QK_WH, QK_WL };
        #pragma unroll
        for (int t = 0; t < 4; t++) {
            char* dst = smem + offs[t];
            #pragma unroll
            for (int i = 0; i < 4; i++) {
                int idx = i * 256 + tid;
                int row = idx >> 3, s = idx & 7;
                *(uint4*)(dst + row * TPAD_B + s * 16) = srcs[t][row * 96 + kt * 8 + s];
            }
        }
        __syncthreads();

        #pragma unroll
        for (int ks = 0; ks < 4; ks++) {
            uint32_t ah[2][4], al[2][4];
            #pragma unroll
            for (int mt = 0; mt < 2; mt++) {
                uint32_t base = (wq + mt * 16) * TPAD_B + ks * 32;
                ldsm4(ah[mt], sb + QK_XH + base + a_roff + a_coff);
                ldsm4(al[mt], sb + QK_XL + base + a_roff + a_coff);
            }
            #pragma unroll
            for (int ng = 0; ng < 4; ng++) {
                uint32_t base = (wn + ng * 16) * TPAD_B + ks * 32;
                uint32_t bhr[4], blr[4];
                ldsm4(bhr, sb + QK_WH + base + b_roff + b_coff);
                ldsm4(blr, sb + QK_WL + base + b_roff + b_coff);
                #pragma unroll
                for (int mt = 0; mt < 2; mt++) {
                    mma16816(acc[mt][2 * ng],     ah[mt], bhr[0], bhr[2]);
                    mma16816(acc[mt][2 * ng + 1], ah[mt], bhr[1], bhr[3]);
                    mma16816(acc[mt][2 * ng],     ah[mt], blr[0], blr[2]);
                    mma16816(acc[mt][2 * ng + 1], ah[mt], blr[1], blr[3]);
                    mma16816(acc[mt][2 * ng],     al[mt], bhr[0], bhr[2]);
                    mma16816(acc[mt][2 * ng + 1], al[mt], bhr[1], bhr[3]);
                }
            }
        }
        __syncthreads();
    }

    if (z == 2) {
        #pragma unroll
        for (int mt = 0; mt < 2; mt++) {
            const int r = m0 + wq + mt * 16 + (lane >> 2);
            #pragma unroll
            for (int nt = 0; nt < 8; nt++) {
                const int cc = n0 + wn + nt * 8 + (lane & 3) * 2;
                *(float2*)(g_V + (size_t)r * DIMM + cc) =
                    make_float2(acc[mt][nt][0], acc[mt][nt][1]);
                *(float2*)(g_V + (size_t)(r + 8) * DIMM + cc) =
                    make_float2(acc[mt][nt][2], acc[mt][nt][3]);
            }
        }
    } else {
        __nv_bfloat16* OH = (z == 0) ? g_Qh : g_Kh;
        __nv_bfloat16* OL = (z == 0) ? g_Ql : g_Kl;
        #pragma unroll
        for (int mt = 0; mt < 2; mt++) {
            const int m = m0 + wq + mt * 16 + (lane >> 2);
            const int b = m >> 11, q = m & 2047;
            #pragma unroll
            for (int nt = 0; nt < 8; nt++) {
                const int n = n0 + wn + nt * 8 + (lane & 3) * 2;
                const int h = n >> 6, d = n & 63;
                size_t base = ((size_t)(b * NH + h) * SEQ + q) * HD + d;
                unsigned lo0, lo1;
                unsigned hi0 = bsplit2(acc[mt][nt][0], acc[mt][nt][1], lo0);
                unsigned hi1 = bsplit2(acc[mt][nt][2], acc[mt][nt][3], lo1);
                *(unsigned*)(OH + base) = hi0;
                *(unsigned*)(OL + base) = lo0;
                *(unsigned*)(OH + base + 8 * HD) = hi1;
                *(unsigned*)(OL + base + 8 * HD) = lo1;
            }
        }
    }
}

// ---------------------------------------------------------------------------
// Kernel 1b: V transpose + split: g_V[b][k][h*64+d] -> g_Vth/l[bh][d][k]
// ---------------------------------------------------------------------------
__global__ void __launch_bounds__(256) k_vsplit()
{
    __shared__ float sh[64][65];
    const int tid = threadIdx.x;
    const int k0 = blockIdx.x * 64;
    const int bh = blockIdx.y;
    const int b = bh / NH, h = bh % NH;

    #pragma unroll
    for (int i = 0; i < 4; i++) {
        int idx4 = i * 256 + tid;
        int kk = idx4 >> 4, c4 = idx4 & 15;
        float4 v = *(const float4*)(g_V + ((size_t)(b * SEQ + k0 + kk)) * DIMM + h * HD + c4 * 4);
        sh[kk][c4 * 4 + 0] = v.x; sh[kk][c4 * 4 + 1] = v.y;
        sh[kk][c4 * 4 + 2] = v.z; sh[kk][c4 * 4 + 3] = v.w;
    }
    __syncthreads();
    #pragma unroll
    for (int i = 0; i < 2; i++) {
        int idx = i * 256 + tid;
        int d = idx >> 3, s = idx & 7;
        unsigned hw[4], lw[4];
        #pragma unroll
        for (int j = 0; j < 2; j++) {
            float4 v = make_float4(sh[s * 8 + j * 4 + 0][d], sh[s * 8 + j * 4 + 1][d],
                                   sh[s * 8 + j * 4 + 2][d], sh[s * 8 + j * 4 + 3][d]);
            uint2 hi, lo; bsplit4(v, hi, lo);
            hw[j * 2] = hi.x; hw[j * 2 + 1] = hi.y;
            lw[j * 2] = lo.x; lw[j * 2 + 1] = lo.y;
        }
        size_t dst = ((size_t)bh * HD + d) * SEQ + k0 + s * 8;
        *(uint4*)(g_Vth + dst) = make_uint4(hw[0], hw[1], hw[2], hw[3]);
        *(uint4*)(g_Vtl + dst) = make_uint4(lw[0], lw[1], lw[2], lw[3]);
    }
}

// ---------------------------------------------------------------------------
// Kernel 2: FUSED escore + dsum. Each CTA owns a (b, 128q, 128k) tile and
// loops all 12 heads: E[bh] tile written per head, D accumulated in the
// position-identical register fragment; Dinv written at the end.
// cp.async double-buffered head tiles (2 x 72KB smem), occ 1.
// ---------------------------------------------------------------------------
#define ESF_BUF 73728
#define ESF_SMEM (2 * ESF_BUF)

__global__ void __launch_bounds__(256) k_escore_fused()
{
    extern __shared__ char smem[];
    const uint32_t sb = smem_u32(smem);
    const int tid = threadIdx.x, wid = tid >> 5, lane = tid & 31;
    const int b  = blockIdx.z;
    const int q0 = blockIdx.y * 128;
    const int k0 = blockIdx.x * 128;

    const uint4* Qh4 = (const uint4*)(g_Qh + ((size_t)(b * NH) * SEQ + q0) * HD);
    const uint4* Ql4 = (const uint4*)(g_Ql + ((size_t)(b * NH) * SEQ + q0) * HD);
    const uint4* Kh4 = (const uint4*)(g_Kh + ((size_t)(b * NH) * SEQ + k0) * HD);
    const uint4* Kl4 = (const uint4*)(g_Kl + ((size_t)(b * NH) * SEQ + k0) * HD);
    const int HSTEP = SEQ * HD / 8;   // per-head offset in uint4

    const int wq = (wid & 3) * 32;
    const int wk = (wid >> 2) * 64;

    const uint32_t a_roff = (lane & 15) * TPAD_B;
    const uint32_t a_coff = (lane >> 4) * 16;
    const uint32_t b_roff = ((lane & 7) + ((lane >> 3) & 1) * 8) * TPAD_B;
    const uint32_t b_coff = (lane >> 4) * 16;

    float dacc[2][8][4];
    #pragma unroll
    for (int mt = 0; mt < 2; mt++)
        #pragma unroll
        for (int nt = 0; nt < 8; nt++)
            #pragma unroll
            for (int j = 0; j < 4; j++) dacc[mt][nt][j] = 0.f;

    // issue loads for head 0 into buffer 0
    {
        const uint4* srcs[4] = { Qh4, Ql4, Kh4, Kl4 };
        const int offs[4] = { 0, 18432, 36864, 55296 };
        #pragma unroll
        for (int t = 0; t < 4; t++)
            #pragma unroll
            for (int i = 0; i < 4; i++) {
                int idx = i * 256 + tid;
                int row = idx >> 3, s = idx & 7;
                cpa16(sb + offs[t] + row * TPAD_B + s * 16, &srcs[t][row * 8 + s]);
            }
        CPA_COMMIT();
    }

    #pragma unroll 1
    for (int h = 0; h < NH; h++) {
        const uint32_t cur = (h & 1) * ESF_BUF;
        if (h + 1 < NH) {
            const uint32_t nxt = ((h + 1) & 1) * ESF_BUF;
            const uint4* srcs[4] = { Qh4 + (h + 1) * HSTEP, Ql4 + (h + 1) * HSTEP,
                                     Kh4 + (h + 1) * HSTEP, Kl4 + (h + 1) * HSTEP };
            const int offs[4] = { 0, 18432, 36864, 55296 };
            #pragma unroll
            for (int t = 0; t < 4; t++)
                #pragma unroll
                for (int i = 0; i < 4; i++) {
                    int idx = i * 256 + tid;
                    int row = idx >> 3, s = idx & 7;
                    cpa16(sb + nxt + offs[t] + row * TPAD_B + s * 16, &srcs[t][row * 8 + s]);
                }
            CPA_COMMIT();
            CPA_WAIT(1);
        } else {
            CPA_WAIT(0);
        }
        __syncthreads();

        float sacc[2][8][4];
        #pragma unroll
        for (int mt = 0; mt < 2; mt++)
            #pragma unroll
            for (int nt = 0; nt < 8; nt++)
                #pragma unroll
                for (int j = 0; j < 4; j++) sacc[mt][nt][j] = 0.f;

        #pragma unroll
        for (int ks = 0; ks < 4; ks++) {
            uint32_t ah[2][4], al[2][4];
            #pragma unroll
            for (int mt = 0; mt < 2; mt++) {
                uint32_t base = cur + (wq + mt * 16) * TPAD_B + ks * 32;
                ldsm4(ah[mt], sb + 0 + base + a_roff + a_coff);
                ldsm4(al[mt], sb + 18432 + base + a_roff + a_coff);
            }
            #pragma unroll
            for (int ng = 0; ng < 4; ng++) {
                uint32_t base = cur + (wk + ng * 16) * TPAD_B + ks * 32;
                uint32_t bhr[4], blr[4];
                ldsm4(bhr, sb + 36864 + base + b_roff + b_coff);
                ldsm4(blr, sb + 55296 + base + b_roff + b_coff);
                #pragma unroll
                for (int mt = 0; mt < 2; mt++) {
                    mma16816(sacc[mt][2 * ng],     ah[mt], bhr[0], bhr[2]);
                    mma16816(sacc[mt][2 * ng + 1], ah[mt], bhr[1], bhr[3]);
                    mma16816(sacc[mt][2 * ng],     ah[mt], blr[0], blr[2]);
                    mma16816(sacc[mt][2 * ng + 1], ah[mt], blr[1], blr[3]);
                    mma16816(sacc[mt][2 * ng],     al[mt], bhr[0], bhr[2]);
                    mma16816(sacc[mt][2 * ng + 1], al[mt], bhr[1], bhr[3]);
                }
            }
        }

        // per-head epilogue: exp, D-accumulate, store E
        float* Eg = g_E + ((size_t)(b * NH + h) * SEQ + q0) * SEQ + k0;
        #pragma unroll
        for (int mt = 0; mt < 2; mt++) {
            const int r = wq + mt * 16 + (lane >> 2);
            #pragma unroll
            for (int nt = 0; nt < 8; nt++) {
                const int cc = wk + nt * 8 + (lane & 3) * 2;
                float e0 = __expf(sacc[mt][nt][0]);
                float e1 = __expf(sacc[mt][nt][1]);
                float e2 = __expf(sacc[mt][nt][2]);
                float e3 = __expf(sacc[mt][nt][3]);
                dacc[mt][nt][0] += e0; dacc[mt][nt][1] += e1;
                dacc[mt][nt][2] += e2; dacc[mt][nt][3] += e3;
                *(float2*)(Eg + (size_t)r * SEQ + cc)       = make_float2(e0, e1);
                *(float2*)(Eg + (size_t)(r + 8) * SEQ + cc) = make_float2(e2, e3);
            }
        }
        __syncthreads();
    }

    // Dinv = (1/sqrt(768)) / D
    const float RS = 0.03608439182435161f;
    float* Dg = g_Dinv + ((size_t)b * SEQ + q0) * SEQ + k0;
    #pragma unroll
    for (int mt = 0; mt < 2; mt++) {
        const int r = wq + mt * 16 + (lane >> 2);
        #pragma unroll
        for (int nt = 0; nt < 8; nt++) {
            const int cc = wk + nt * 8 + (lane & 3) * 2;
            *(float2*)(Dg + (size_t)r * SEQ + cc) =
                make_float2(RS / dacc[mt][nt][0], RS / dacc[mt][nt][1]);
            *(float2*)(Dg + (size_t)(r + 8) * SEQ + cc) =
                make_float2(RS / dacc[mt][nt][2], RS / dacc[mt][nt][3]);
        }
    }
}

// ---------------------------------------------------------------------------
// Kernel 4: out = (E*Dinv) @ V via mma.sync, P split to bf16 on the fly.
// ---------------------------------------------------------------------------
#define AV_PH 0
#define AV_PL 18432
#define AV_VH 36864
#define AV_VL 46080
#define AV_SMEM 55296

__global__ void __launch_bounds__(256) k_av_mma(float* __restrict__ out)
{
    extern __shared__ char smem[];
    const uint32_t sb = smem_u32(smem);
    const int tid = threadIdx.x, wid = tid >> 5, lane = tid & 31;
    const int h = blockIdx.x, b = blockIdx.z;
    const int bh = b * NH + h;
    const int q0 = blockIdx.y * 128;

    const float* Eb = g_E    + ((size_t)bh * SEQ + q0) * SEQ;
    const float* Db = g_Dinv + ((size_t)b  * SEQ + q0) * SEQ;
    const uint4* Vh4 = (const uint4*)(g_Vth + (size_t)bh * HD * SEQ);
    const uint4* Vl4 = (const uint4*)(g_Vtl + (size_t)bh * HD * SEQ);

    const int wq = (wid & 3) * 32;
    const int wd = (wid >> 2) * 32;

    float acc[2][4][4];
    #pragma unroll
    for (int mt = 0; mt < 2; mt++)
        #pragma unroll
        for (int nt = 0; nt < 4; nt++)
            #pragma unroll
            for (int j = 0; j < 4; j++) acc[mt][nt][j] = 0.f;

    const uint32_t a_roff = (lane & 15) * TPAD_B;
    const uint32_t a_coff = (lane >> 4) * 16;
    const uint32_t b_roff = ((lane & 7) + ((lane >> 3) & 1) * 8) * TPAD_B;
    const uint32_t b_coff = (lane >> 4) * 16;

    for (int kc = 0; kc < 32; kc++) {
        #pragma unroll
        for (int i = 0; i < 2; i++) {
            int idx = i * 256 + tid;
            int d = idx >> 3, s = idx & 7;
            *(uint4*)(smem + AV_VH + d * TPAD_B + s * 16) = Vh4[d * 256 + kc * 8 + s];
            *(uint4*)(smem + AV_VL + d * TPAD_B + s * 16) = Vl4[d * 256 + kc * 8 + s];
        }
        #pragma unroll
        for (int i = 0; i < 8; i++) {
            int idx = i * 256 + tid;
            int r = idx >> 4, c4 = idx & 15;
            float4 e  = *(const float4*)(Eb + (size_t)r * SEQ + kc * 64 + c4 * 4);
            float4 dn = *(const float4*)(Db + (size_t)r * SEQ + kc * 64 + c4 * 4);
            float4 p = make_float4(e.x * dn.x, e.y * dn.y, e.z * dn.z, e.w * dn.w);
            uint2 hi, lo; bsplit4(p, hi, lo);
            *(uint2*)(smem + AV_PH + r * TPAD_B + c4 * 8) = hi;
            *(uint2*)(smem + AV_PL + r * TPAD_B + c4 * 8) = lo;
        }
        __syncthreads();

        #pragma unroll
        for (int ks = 0; ks < 4; ks++) {
            uint32_t ah[2][4], al[2][4];
            #pragma unroll
            for (int mt = 0; mt < 2; mt++) {
                uint32_t base = (wq + mt * 16) * TPAD_B + ks * 32;
                ldsm4(ah[mt], sb + AV_PH + base + a_roff + a_coff);
                ldsm4(al[mt], sb + AV_PL + base + a_roff + a_coff);
            }
            #pragma unroll
            for (int ng = 0; ng < 2; ng++) {
                uint32_t base = (wd + ng * 16) * TPAD_B + ks * 32;
                uint32_t bhr[4], blr[4];
                ldsm4(bhr, sb + AV_VH + base + b_roff + b_coff);
                ldsm4(blr, sb + AV_VL + base + b_roff + b_coff);
                #pragma unroll
                for (int mt = 0; mt < 2; mt++) {
                    mma16816(acc[mt][2 * ng],     ah[mt], bhr[0], bhr[2]);
                    mma16816(acc[mt][2 * ng + 1], ah[mt], bhr[1], bhr[3]);
                    mma16816(acc[mt][2 * ng],     ah[mt], blr[0], blr[2]);
                    mma16816(acc[mt][2 * ng + 1], ah[mt], blr[1], blr[3]);
                    mma16816(acc[mt][2 * ng],     al[mt], bhr[0], bhr[2]);
                    mma16816(acc[mt][2 * ng + 1], al[mt], bhr[1], bhr[3]);
                }
            }
        }
        __syncthreads();
    }

    float* Og = out + ((size_t)(b * SEQ + q0)) * DIMM + h * HD;
    #pragma unroll
    for (int mt = 0; mt < 2; mt++) {
        const int r = wq + mt * 16 + (lane >> 2);
        #pragma unroll
        for (int nt = 0; nt < 4; nt++) {
            const int cc = wd + nt * 8 + (lane & 3) * 2;
            *(float2*)(Og + (size_t)r * DIMM + cc) =
                make_float2(acc[mt][nt][0], acc[mt][nt][1]);
            *(float2*)(Og + (size_t)(r + 8) * DIMM + cc) =
                make_float2(acc[mt][nt][2], acc[mt][nt][3]);
        }
    }
}

// ---------------------------------------------------------------------------
extern "C" void kernel_launch(void* const* d_in, const int* in_sizes, int n_in,
                              void* d_out, int out_size)
{
    const float* x  = (const float*)d_in[0];
    const float* wq = (const float*)d_in[1];
    const float* wk = (const float*)d_in[2];
    const float* wv = (const float*)d_in[3];
    float* out = (float*)d_out;

    cudaFuncSetAttribute(k_qkv_mma,      cudaFuncAttributeMaxDynamicSharedMemorySize, QK_SMEM);
    cudaFuncSetAttribute(k_escore_fused, cudaFuncAttributeMaxDynamicSharedMemorySize, ESF_SMEM);
    cudaFuncSetAttribute(k_av_mma,       cudaFuncAttributeMaxDynamicSharedMemorySize, AV_SMEM);

    __nv_bfloat16 *xh, *xl, *wh, *wl;
    cudaGetSymbolAddress((void**)&xh, g_Xh);
    cudaGetSymbolAddress((void**)&xl, g_Xl);
    cudaGetSymbolAddress((void**)&wh, g_Wh);
    cudaGetSymbolAddress((void**)&wl, g_Wl);

    k_split<<<3072, 256>>>(x,  xh, xl, 786432);                       // X
    k_split<<<576,  256>>>(wq, wh,               wl,               147456);
    k_split<<<576,  256>>>(wk, wh + 589824,      wl + 589824,      147456);
    k_split<<<576,  256>>>(wv, wh + 1179648,     wl + 1179648,     147456);
    k_qkv_mma     <<<dim3(6, 32, 3),  256, QK_SMEM>>>();
    k_vsplit      <<<dim3(32, 24),    256>>>();
    k_escore_fused<<<dim3(16, 16, 2), 256, ESF_SMEM>>>();
    k_av_mma      <<<dim3(12, 16, 2), 256, AV_SMEM>>>(out);
}